// round 14
// baseline (speedup 1.0000x reference)
#include <cuda_runtime.h>
#include <math.h>

// Problem constants: B=2, L=128, H=768, C=6, nhops=2
#define NC  6
#define LL  128
#define WS  1600     // WT row stride (1554 padded)

// Scratch (allocation-free: __device__ globals)
__device__ __align__(16) float g_WcT[NC * WS];       // (feat_w@cls_w)^T [c][k], k<1554
__device__ __align__(16) float g_W2T[NC * WS];       // (feat_w@Wc1)^T   [c][k], k<1554
__device__ float g_fbc[NC];                          // feat_b @ cls_w
__device__ float g_fbW2[NC];                         // feat_b @ Wc1
__device__ float g_pqr0[513 * NC], g_pool0[256 * NC];
__device__ float g_pqr1[513 * NC], g_pool1[256 * NC];
__device__ float g_pqr2f[513 * NC];

// ================= (1) hop0: p0/q0 + masked max-pool =================
// 12 blocks (b,c) x 256 threads
__global__ void k_pp0(const float* __restrict__ hidden, const float* __restrict__ cls_w,
                      const float* __restrict__ cls_b, const float* __restrict__ am) {
    int b = blockIdx.x / NC, c = blockIdx.x % NC;
    __shared__ float sw[1536];
    __shared__ float sp[LL], sq[LL], sm[LL], sm1[LL], sm2[LL];
    int tid = threadIdx.x;
    for (int e = tid; e < 1536; e += 256) sw[e] = cls_w[e * NC + c];
    __syncthreads();
    int k = tid & 127, isq = tid >> 7;               // half 0: p-dot, half 1: q-dot
    {
        const float4* hr = (const float4*)(hidden + (size_t)(b * LL + k) * 768);
        const float4* w  = (const float4*)(sw + isq * 768);
        float s = 0.f;
        #pragma unroll 4
        for (int it = 0; it < 192; it++) {
            float4 a = hr[it], x = w[it];
            s += a.x * x.x + a.y * x.y + a.z * x.z + a.w * x.w;
        }
        if (isq) sq[k] = s; else { sp[k] = s; sm[k] = am[b * LL + k]; }
    }
    __syncthreads();
    float r  = cls_b[c];
    float mk = sm[k], pk = sp[k], qk = sq[k];
    float mx = -INFINITY;
    if (isq == 0) {                                  // column k: over i <= k
        #pragma unroll 4
        for (int i = 0; i < LL; i++) {
            float mv = (i <= k) ? sm[i] * mk : 0.f;
            mx = fmaxf(mx, (sp[i] + qk + r) * mv);
        }
        sm1[k] = mx;
    } else {                                         // row k: over j >= k
        #pragma unroll 4
        for (int i = 0; i < LL; i++) {
            float mv = (i >= k) ? mk * sm[i] : 0.f;
            mx = fmaxf(mx, (pk + sq[i] + r) * mv);
        }
        sm2[k] = mx;
    }
    __syncthreads();
    if (isq) return;
    int rw = b * LL + k;
    g_pool0[rw * NC + c] = fmaxf(sm1[k], sm2[k]);
    g_pqr0[rw * NC + c] = pk;
    g_pqr0[(256 + rw) * NC + c] = qk;
    if (b == 0 && k == 0) g_pqr0[512 * NC + c] = r;
}

// ================= (2,3) weight condensation, blocked =================
// which=0: Wc = feat_w @ cls_w (stage from cls_w, transposing)
// which=1: W2 = feat_w @ Wc1   (stage from g_WcT rows)
// 99 blocks x 256: blocks 0..97 -> 16 k-rows each (2 per warp); block 98 -> feat_b dots.
__global__ void __launch_bounds__(256) k_dotW(const float* __restrict__ feat_w,
                                              const float* __restrict__ feat_b,
                                              const float* __restrict__ cls_w, int which) {
    __shared__ float sw[NC * 1536];                  // 36 KB channel vectors
    int tid = threadIdx.x;
    int blk = blockIdx.x;
    for (int idx = tid; idx < NC * 1536; idx += 256) {
        int c = idx / 1536, k = idx % 1536;
        sw[idx] = which ? g_WcT[c * WS + k] : cls_w[k * NC + c];
    }
    __syncthreads();
    int w = tid >> 5, lane = tid & 31;
    const float4* swv = (const float4*)sw;
    if (blk < 98) {
        int k0 = blk * 16 + w * 2;                   // rows k0, k0+1
        bool v0 = (k0 < 1554), v1 = (k0 + 1 < 1554);
        const float4* f0 = (const float4*)(feat_w + (size_t)k0 * 1536);
        const float4* f1 = (const float4*)(feat_w + (size_t)(k0 + 1) * 1536);
        float s[2][NC];
        #pragma unroll
        for (int r = 0; r < 2; r++)
            #pragma unroll
            for (int c = 0; c < NC; c++) s[r][c] = 0.f;
        #pragma unroll 4
        for (int it = 0; it < 12; it++) {
            int col = it * 32 + lane;
            float4 a0 = v0 ? f0[col] : make_float4(0.f, 0.f, 0.f, 0.f);
            float4 a1 = v1 ? f1[col] : make_float4(0.f, 0.f, 0.f, 0.f);
            #pragma unroll
            for (int c = 0; c < NC; c++) {
                float4 wv = swv[c * 384 + col];
                s[0][c] += a0.x * wv.x + a0.y * wv.y + a0.z * wv.z + a0.w * wv.w;
                s[1][c] += a1.x * wv.x + a1.y * wv.y + a1.z * wv.z + a1.w * wv.w;
            }
        }
        #pragma unroll
        for (int r = 0; r < 2; r++)
            #pragma unroll
            for (int c = 0; c < NC; c++) {
                float v = s[r][c];
                #pragma unroll
                for (int o = 16; o; o >>= 1) v += __shfl_down_sync(0xffffffffu, v, o);
                if (lane == 0) {
                    int k = k0 + r;
                    float outv = (k < 1554) ? v : 0.f;
                    if (which) g_W2T[c * WS + k] = outv;
                    else       g_WcT[c * WS + k] = outv;
                }
            }
    } else if (w < NC) {                             // feat_b . channel[w]
        const float4* fb = (const float4*)feat_b;
        const float4* cv = swv + w * 384;
        float s = 0.f;
        #pragma unroll 4
        for (int it = 0; it < 12; it++) {
            int col = it * 32 + lane;
            float4 a = fb[col], b = cv[col];
            s += a.x * b.x + a.y * b.y + a.z * b.z + a.w * b.w;
        }
        #pragma unroll
        for (int o = 16; o; o >>= 1) s += __shfl_down_sync(0xffffffffu, s, o);
        if (lane == 0) { if (which) g_fbW2[w] = s; else g_fbc[w] = s; }
    }
}

// ================= (4) probs1 = A0ext @ Wc (+ const-row terms) =================
// 513 blocks x 192 threads
__global__ void k_probs1(const float* __restrict__ hidden, const float* __restrict__ cls_b) {
    int row = blockIdx.x;
    int c = threadIdx.x >> 5, lane = threadIdx.x & 31;
    float s = 0.f;
    if (row < 512) {
        const float4* hr = (const float4*)(hidden + (size_t)(row < 256 ? row : row - 256) * 768);
        const float4* wr = (const float4*)(g_WcT + (size_t)c * WS + (row < 256 ? 0 : 768));
        #pragma unroll
        for (int it = 0; it < 6; it++) {
            int k4 = it * 32 + lane;
            float4 a = hr[k4], b = wr[k4];
            s += a.x * b.x + a.y * b.y + a.z * b.z + a.w * b.w;
        }
    }
    #pragma unroll
    for (int o = 16; o; o >>= 1) s += __shfl_down_sync(0xffffffffu, s, o);
    if (lane == 0) {
        const float* wt = g_WcT + (size_t)c * WS + 1536;
        if (row < 256) {
            #pragma unroll
            for (int t = 0; t < 6; t++) s += g_pool0[row * NC + t] * wt[t];
        } else if (row < 512) {
            #pragma unroll
            for (int t = 0; t < 6; t++) s += g_pool0[(row - 256) * NC + t] * wt[6 + t];
        }
        #pragma unroll
        for (int t = 0; t < 6; t++) s += g_pqr0[row * NC + t] * wt[12 + t];
        if (row == 512) s += g_fbc[c] + cls_b[c];
        g_pqr1[row * NC + c] = s;
    }
}

// ================= (5) pool1 from pqr1 =================
__global__ void k_pool1(const float* __restrict__ am) {
    int b = blockIdx.x / NC, c = blockIdx.x % NC;
    __shared__ float sp[LL], sq[LL], sm[LL];
    int k = threadIdx.x;
    sp[k] = g_pqr1[(b * LL + k) * NC + c];
    sq[k] = g_pqr1[(256 + b * LL + k) * NC + c];
    sm[k] = am[b * LL + k];
    __syncthreads();
    float r  = g_pqr1[512 * NC + c];
    float mk = sm[k], pk = sp[k], qk = sq[k];
    float mx = -INFINITY;
    #pragma unroll 4
    for (int i = 0; i < LL; i++) {
        float mi  = sm[i];
        float mv1 = (i <= k) ? mi * mk : 0.f;
        mx = fmaxf(mx, (sp[i] + qk + r) * mv1);
        float mv2 = (i >= k) ? mk * mi : 0.f;
        mx = fmaxf(mx, (pk + sq[i] + r) * mv2);
    }
    g_pool1[(b * LL + k) * NC + c] = mx;
}

// ================= (6) probs2 = A0ext @ W2 + ext1 @ Wc_tail (+ const-row) =================
__global__ void k_probs2(const float* __restrict__ hidden, const float* __restrict__ cls_b) {
    int row = blockIdx.x;
    int c = threadIdx.x >> 5, lane = threadIdx.x & 31;
    float s = 0.f;
    if (row < 512) {
        const float4* hr = (const float4*)(hidden + (size_t)(row < 256 ? row : row - 256) * 768);
        const float4* wr = (const float4*)(g_W2T + (size_t)c * WS + (row < 256 ? 0 : 768));
        #pragma unroll
        for (int it = 0; it < 6; it++) {
            int k4 = it * 32 + lane;
            float4 a = hr[k4], b = wr[k4];
            s += a.x * b.x + a.y * b.y + a.z * b.z + a.w * b.w;
        }
    }
    #pragma unroll
    for (int o = 16; o; o >>= 1) s += __shfl_down_sync(0xffffffffu, s, o);
    if (lane == 0) {
        const float* w2t = g_W2T + (size_t)c * WS + 1536;
        const float* wct = g_WcT + (size_t)c * WS + 1536;
        if (row < 256) {
            #pragma unroll
            for (int t = 0; t < 6; t++)
                s += g_pool0[row * NC + t] * w2t[t] + g_pool1[row * NC + t] * wct[t];
        } else if (row < 512) {
            #pragma unroll
            for (int t = 0; t < 6; t++)
                s += g_pool0[(row - 256) * NC + t] * w2t[6 + t] + g_pool1[(row - 256) * NC + t] * wct[6 + t];
        }
        #pragma unroll
        for (int t = 0; t < 6; t++)
            s += g_pqr0[row * NC + t] * w2t[12 + t] + g_pqr1[row * NC + t] * wct[12 + t];
        if (row == 512) s += g_fbW2[c] + g_fbc[c] + cls_b[c];
        g_pqr2f[row * NC + c] = s;
    }
}

// ================= (7) final: logits[b,i,j,c] = p + q + r =================
__global__ void k_out(float* __restrict__ out) {
    int idx = blockIdx.x * 256 + threadIdx.x;        // 0..196607 exact
    int c = idx % NC;
    int j = (idx / NC) % LL;
    int t = idx / (NC * LL);
    int i = t % LL;
    int b = t / LL;
    out[idx] = g_pqr2f[(b * LL + i) * NC + c]
             + g_pqr2f[(256 + b * LL + j) * NC + c]
             + g_pqr2f[512 * NC + c];
}

extern "C" void kernel_launch(void* const* d_in, const int* in_sizes, int n_in,
                              void* d_out, int out_size) {
    const float* hidden = (const float*)d_in[0];
    const float* am     = (const float*)d_in[1];
    const float* cls_w  = (const float*)d_in[2];
    const float* cls_b  = (const float*)d_in[3];
    const float* feat_w = (const float*)d_in[4];
    const float* feat_b = (const float*)d_in[5];

    k_pp0<<<12, 256>>>(hidden, cls_w, cls_b, am);    // (1)
    k_dotW<<<99, 256>>>(feat_w, feat_b, cls_w, 0);   // (2) Wc
    k_dotW<<<99, 256>>>(feat_w, feat_b, cls_w, 1);   // (3) W2
    k_probs1<<<513, 192>>>(hidden, cls_b);           // (4) <- profiled
    k_pool1<<<12, 128>>>(am);                        // (5)
    k_probs2<<<513, 192>>>(hidden, cls_b);           // (6)
    k_out<<<768, 256>>>((float*)d_out);              // (7)
}

// round 15
// speedup vs baseline: 1.2463x; 1.2463x over previous
#include <cuda_runtime.h>
#include <math.h>

// Problem constants: B=2, L=128, H=768, C=6, nhops=2
#define NC  6
#define LL  128
#define WS  1600     // WT row stride (1554 padded)

// Scratch (allocation-free: __device__ globals)
__device__ __align__(16) float g_WcT[NC * WS];       // (feat_w@cls_w)^T [c][k], k<1554
__device__ __align__(16) float g_W2T[NC * WS];       // (feat_w@Wc1)^T   [c][k], k<1554
__device__ float g_fbc[NC];                          // feat_b @ cls_w
__device__ float g_fbW2[NC];                         // feat_b @ Wc1
__device__ float g_pqr0[513 * NC], g_pool0[256 * NC];
__device__ float g_pqr1[513 * NC];
__device__ float g_pqr2f[513 * NC];

// ---- shared dotW body: 512 threads, 16 warps x 2 rows = 32 k-rows per block ----
// blk2 in [0,49): rows; blk2 == 49: feat_b dots.
__device__ __forceinline__ void dotW_body(float* sbuf, int blk2,
                                          const float* __restrict__ feat_w,
                                          const float* __restrict__ feat_b,
                                          const float* __restrict__ cls_w, int which) {
    int tid = threadIdx.x;
    for (int idx = tid; idx < NC * 1536; idx += 512) {
        int c = idx / 1536, k = idx % 1536;
        sbuf[idx] = which ? g_WcT[c * WS + k] : cls_w[k * NC + c];
    }
    __syncthreads();
    int w = tid >> 5, lane = tid & 31;
    const float4* swv = (const float4*)sbuf;
    if (blk2 < 49) {
        int k0 = blk2 * 32 + w * 2;                  // rows k0, k0+1
        bool v0 = (k0 < 1554), v1 = (k0 + 1 < 1554);
        const float4* f0 = (const float4*)(feat_w + (size_t)k0 * 1536);
        const float4* f1 = (const float4*)(feat_w + (size_t)(k0 + 1) * 1536);
        float s[2][NC];
        #pragma unroll
        for (int r = 0; r < 2; r++)
            #pragma unroll
            for (int c = 0; c < NC; c++) s[r][c] = 0.f;
        #pragma unroll 4
        for (int it = 0; it < 12; it++) {
            int col = it * 32 + lane;
            float4 a0 = v0 ? f0[col] : make_float4(0.f, 0.f, 0.f, 0.f);
            float4 a1 = v1 ? f1[col] : make_float4(0.f, 0.f, 0.f, 0.f);
            #pragma unroll
            for (int c = 0; c < NC; c++) {
                float4 wv = swv[c * 384 + col];
                s[0][c] += a0.x * wv.x + a0.y * wv.y + a0.z * wv.z + a0.w * wv.w;
                s[1][c] += a1.x * wv.x + a1.y * wv.y + a1.z * wv.z + a1.w * wv.w;
            }
        }
        #pragma unroll
        for (int r = 0; r < 2; r++)
            #pragma unroll
            for (int c = 0; c < NC; c++) {
                float v = s[r][c];
                #pragma unroll
                for (int o = 16; o; o >>= 1) v += __shfl_down_sync(0xffffffffu, v, o);
                if (lane == 0) {
                    int k = k0 + r;
                    if (k < WS) {
                        float outv = (k < 1554) ? v : 0.f;
                        if (which) g_W2T[c * WS + k] = outv;
                        else       g_WcT[c * WS + k] = outv;
                    }
                }
            }
    } else if (w < NC) {
        const float4* fb = (const float4*)feat_b;
        const float4* cv = swv + w * 384;
        float s = 0.f;
        #pragma unroll 4
        for (int it = 0; it < 12; it++) {
            int col = it * 32 + lane;
            float4 a = fb[col], b = cv[col];
            s += a.x * b.x + a.y * b.y + a.z * b.z + a.w * b.w;
        }
        #pragma unroll
        for (int o = 16; o; o >>= 1) s += __shfl_down_sync(0xffffffffu, s, o);
        if (lane == 0) { if (which) g_fbW2[w] = s; else g_fbc[w] = s; }
    }
}

// ================= kA: pp0 (blocks 0..11) || dotW0 (blocks 12..61) =================
__global__ void __launch_bounds__(512) kA(const float* __restrict__ hidden,
                                          const float* __restrict__ cls_w,
                                          const float* __restrict__ cls_b,
                                          const float* __restrict__ am,
                                          const float* __restrict__ feat_w,
                                          const float* __restrict__ feat_b) {
    __shared__ float sbuf[9216];                     // 36 KB
    int tid = threadIdx.x;
    if (blockIdx.x >= 12) {
        dotW_body(sbuf, blockIdx.x - 12, feat_w, feat_b, cls_w, 0);
        return;
    }
    // ---- pp0: hop0 p0/q0 + masked max-pool, dot split over 2 half-threads ----
    int b = blockIdx.x / NC, c = blockIdx.x % NC;
    float* sw  = sbuf;          // 1536
    float* sp  = sbuf + 1536;
    float* sq  = sbuf + 1664;
    float* smm = sbuf + 1792;
    float* sm1 = sbuf + 1920;
    float* sm2 = sbuf + 2048;
    float* part = sbuf + 2176;  // 512
    for (int e = tid; e < 1536; e += 512) sw[e] = cls_w[e * NC + c];
    __syncthreads();
    int k = tid & 127, isq = (tid >> 7) & 1, hh = tid >> 8;
    {
        const float4* hr = (const float4*)(hidden + (size_t)(b * LL + k) * 768);
        const float4* w4 = (const float4*)(sw + isq * 768);
        float s = 0.f;
        #pragma unroll 4
        for (int it = 0; it < 96; it++) {
            int col = hh * 96 + it;
            float4 a = hr[col], x = w4[col];
            s += a.x * x.x + a.y * x.y + a.z * x.z + a.w * x.w;
        }
        part[tid] = s;
    }
    __syncthreads();
    if (tid < 256) {
        float s2 = part[tid] + part[tid + 256];
        if (isq) sq[k] = s2; else { sp[k] = s2; smm[k] = am[b * LL + k]; }
    }
    __syncthreads();
    float r = cls_b[c];
    if (tid < 256) {
        float mk = smm[k], pk = sp[k], qk = sq[k];
        float mx = -INFINITY;
        if (isq == 0) {                              // column k: over i <= k
            #pragma unroll 4
            for (int i = 0; i < LL; i++) {
                float mv = (i <= k) ? smm[i] * mk : 0.f;
                mx = fmaxf(mx, (sp[i] + qk + r) * mv);
            }
            sm1[k] = mx;
        } else {                                     // row k: over j >= k
            #pragma unroll 4
            for (int i = 0; i < LL; i++) {
                float mv = (i >= k) ? mk * smm[i] : 0.f;
                mx = fmaxf(mx, (pk + sq[i] + r) * mv);
            }
            sm2[k] = mx;
        }
    }
    __syncthreads();
    if (tid < 256 && isq == 0) {
        int rw = b * LL + k;
        g_pool0[rw * NC + c] = fmaxf(sm1[k], sm2[k]);
        g_pqr0[rw * NC + c] = sp[k];
        g_pqr0[(256 + rw) * NC + c] = sq[k];
        if (b == 0 && k == 0) g_pqr0[512 * NC + c] = r;
    }
}

// ================= kB: dotW1 (blocks 0..49) || probs1 (blocks 50..306, 2 rows each) ====
__global__ void __launch_bounds__(512) kB(const float* __restrict__ hidden,
                                          const float* __restrict__ cls_w,
                                          const float* __restrict__ cls_b,
                                          const float* __restrict__ feat_w,
                                          const float* __restrict__ feat_b) {
    __shared__ float sbuf[9216];
    if (blockIdx.x < 50) {
        dotW_body(sbuf, blockIdx.x, feat_w, feat_b, cls_w, 1);
        return;
    }
    int w = threadIdx.x >> 5, lane = threadIdx.x & 31;
    if (w >= 12) return;
    int row = (blockIdx.x - 50) * 2 + (w / 6);
    int c = w % 6;
    if (row >= 513) return;
    float s = 0.f;
    if (row < 512) {
        const float4* hr = (const float4*)(hidden + (size_t)(row < 256 ? row : row - 256) * 768);
        const float4* wr = (const float4*)(g_WcT + (size_t)c * WS + (row < 256 ? 0 : 768));
        #pragma unroll
        for (int it = 0; it < 6; it++) {
            int k4 = it * 32 + lane;
            float4 a = hr[k4], b = wr[k4];
            s += a.x * b.x + a.y * b.y + a.z * b.z + a.w * b.w;
        }
    }
    #pragma unroll
    for (int o = 16; o; o >>= 1) s += __shfl_down_sync(0xffffffffu, s, o);
    if (lane == 0) {
        const float* wt = g_WcT + (size_t)c * WS + 1536;
        if (row < 256) {
            #pragma unroll
            for (int t = 0; t < 6; t++) s += g_pool0[row * NC + t] * wt[t];
        } else if (row < 512) {
            #pragma unroll
            for (int t = 0; t < 6; t++) s += g_pool0[(row - 256) * NC + t] * wt[6 + t];
        }
        #pragma unroll
        for (int t = 0; t < 6; t++) s += g_pqr0[row * NC + t] * wt[12 + t];
        if (row == 512) s += g_fbc[c] + cls_b[c];
        g_pqr1[row * NC + c] = s;
    }
}

// ================= kC: probs2 with inline pool1 (513 blocks x 192) =================
__global__ void kC(const float* __restrict__ hidden, const float* __restrict__ cls_b,
                   const float* __restrict__ am) {
    __shared__ float spool[NC];
    int row = blockIdx.x;
    int c = threadIdx.x >> 5, lane = threadIdx.x & 31;
    float s = 0.f;
    if (row < 512) {
        const float4* hr = (const float4*)(hidden + (size_t)(row < 256 ? row : row - 256) * 768);
        const float4* wr = (const float4*)(g_W2T + (size_t)c * WS + (row < 256 ? 0 : 768));
        #pragma unroll
        for (int it = 0; it < 6; it++) {
            int k4 = it * 32 + lane;
            float4 a = hr[k4], b = wr[k4];
            s += a.x * b.x + a.y * b.y + a.z * b.z + a.w * b.w;
        }
    }
    #pragma unroll
    for (int o = 16; o; o >>= 1) s += __shfl_down_sync(0xffffffffu, s, o);
    // warp c computes pooled1[rw][c] from pqr1 (exact same mask/max as reference)
    if (row < 512) {
        int rw = (row < 256) ? row : row - 256;
        int b = rw >> 7, k = rw & 127;
        float mk  = am[b * LL + k];
        float pk1 = g_pqr1[(b * LL + k) * NC + c];
        float qk1 = g_pqr1[(256 + b * LL + k) * NC + c];
        float r1  = g_pqr1[512 * NC + c];
        float mx = -INFINITY;
        #pragma unroll
        for (int u = 0; u < 4; u++) {
            int i = lane + u * 32;
            float mi = am[b * LL + i];
            float mv1 = (i <= k) ? mi * mk : 0.f;    // column k over i
            mx = fmaxf(mx, (g_pqr1[(b * LL + i) * NC + c] + qk1 + r1) * mv1);
            float mv2 = (i >= k) ? mk * mi : 0.f;    // row k over j
            mx = fmaxf(mx, (pk1 + g_pqr1[(256 + b * LL + i) * NC + c] + r1) * mv2);
        }
        #pragma unroll
        for (int o = 16; o; o >>= 1) mx = fmaxf(mx, __shfl_down_sync(0xffffffffu, mx, o));
        if (lane == 0) spool[c] = mx;
    }
    __syncthreads();
    if (lane == 0) {
        const float* w2t = g_W2T + (size_t)c * WS + 1536;
        const float* wct = g_WcT + (size_t)c * WS + 1536;
        if (row < 256) {
            #pragma unroll
            for (int t = 0; t < 6; t++)
                s += g_pool0[row * NC + t] * w2t[t] + spool[t] * wct[t];
        } else if (row < 512) {
            #pragma unroll
            for (int t = 0; t < 6; t++)
                s += g_pool0[(row - 256) * NC + t] * w2t[6 + t] + spool[t] * wct[6 + t];
        }
        #pragma unroll
        for (int t = 0; t < 6; t++)
            s += g_pqr0[row * NC + t] * w2t[12 + t] + g_pqr1[row * NC + t] * wct[12 + t];
        if (row == 512) s += g_fbW2[c] + g_fbc[c] + cls_b[c];
        g_pqr2f[row * NC + c] = s;
    }
}

// ================= kD: final logits[b,i,j,c] = p + q + r =================
__global__ void k_out(float* __restrict__ out) {
    int idx = blockIdx.x * 256 + threadIdx.x;        // 0..196607 exact
    int c = idx % NC;
    int j = (idx / NC) % LL;
    int t = idx / (NC * LL);
    int i = t % LL;
    int b = t / LL;
    out[idx] = g_pqr2f[(b * LL + i) * NC + c]
             + g_pqr2f[(256 + b * LL + j) * NC + c]
             + g_pqr2f[512 * NC + c];
}

extern "C" void kernel_launch(void* const* d_in, const int* in_sizes, int n_in,
                              void* d_out, int out_size) {
    const float* hidden = (const float*)d_in[0];
    const float* am     = (const float*)d_in[1];
    const float* cls_w  = (const float*)d_in[2];
    const float* cls_b  = (const float*)d_in[3];
    const float* feat_w = (const float*)d_in[4];
    const float* feat_b = (const float*)d_in[5];

    kA<<<62, 512>>>(hidden, cls_w, cls_b, am, feat_w, feat_b);   // pp0 || Wc
    kB<<<307, 512>>>(hidden, cls_w, cls_b, feat_w, feat_b);      // W2 || probs1
    kC<<<513, 192>>>(hidden, cls_b, am);                         // probs2 + inline pool1
    k_out<<<768, 256>>>((float*)d_out);                          // logits
}

// round 16
// speedup vs baseline: 1.2581x; 1.0094x over previous
#include <cuda_runtime.h>
#include <math.h>

// Problem constants: B=2, L=128, H=768, C=6, nhops=2
#define NC  6
#define LL  128
#define WS  1600     // WT row stride (1554 padded)

// Scratch (allocation-free: __device__ globals)
__device__ __align__(16) float g_WcT[NC * WS];       // (feat_w@cls_w)^T [c][k], k<1554
__device__ __align__(16) float g_W2T[NC * WS];       // (feat_w@Wc1)^T   [c][k], k<1554
__device__ float g_fbc[NC];                          // feat_b @ cls_w
__device__ float g_fbW2[NC];                         // feat_b @ Wc1
__device__ float g_pqr0[513 * NC], g_pool0[256 * NC];
__device__ float g_pqr1[513 * NC];
__device__ __align__(16) float g_pqr2f[513 * NC + 2];  // +pad for float4 tail reads

// ---- shared dotW body: 512 threads, 16 warps x 2 rows = 32 k-rows per block ----
// blk2 in [0,49): rows; blk2 == 49: feat_b dots.
__device__ __forceinline__ void dotW_body(float* sbuf, int blk2,
                                          const float* __restrict__ feat_w,
                                          const float* __restrict__ feat_b,
                                          const float* __restrict__ cls_w, int which) {
    int tid = threadIdx.x;
    for (int idx = tid; idx < NC * 1536; idx += 512) {
        int c = idx / 1536, k = idx % 1536;
        sbuf[idx] = which ? g_WcT[c * WS + k] : cls_w[k * NC + c];
    }
    __syncthreads();
    int w = tid >> 5, lane = tid & 31;
    const float4* swv = (const float4*)sbuf;
    if (blk2 < 49) {
        int k0 = blk2 * 32 + w * 2;                  // rows k0, k0+1
        bool v0 = (k0 < 1554), v1 = (k0 + 1 < 1554);
        const float4* f0 = (const float4*)(feat_w + (size_t)k0 * 1536);
        const float4* f1 = (const float4*)(feat_w + (size_t)(k0 + 1) * 1536);
        float s[2][NC];
        #pragma unroll
        for (int r = 0; r < 2; r++)
            #pragma unroll
            for (int c = 0; c < NC; c++) s[r][c] = 0.f;
        #pragma unroll 4
        for (int it = 0; it < 12; it++) {
            int col = it * 32 + lane;
            float4 a0 = v0 ? f0[col] : make_float4(0.f, 0.f, 0.f, 0.f);
            float4 a1 = v1 ? f1[col] : make_float4(0.f, 0.f, 0.f, 0.f);
            #pragma unroll
            for (int c = 0; c < NC; c++) {
                float4 wv = swv[c * 384 + col];
                s[0][c] += a0.x * wv.x + a0.y * wv.y + a0.z * wv.z + a0.w * wv.w;
                s[1][c] += a1.x * wv.x + a1.y * wv.y + a1.z * wv.z + a1.w * wv.w;
            }
        }
        #pragma unroll
        for (int r = 0; r < 2; r++)
            #pragma unroll
            for (int c = 0; c < NC; c++) {
                float v = s[r][c];
                #pragma unroll
                for (int o = 16; o; o >>= 1) v += __shfl_down_sync(0xffffffffu, v, o);
                if (lane == 0) {
                    int k = k0 + r;
                    if (k < WS) {
                        float outv = (k < 1554) ? v : 0.f;
                        if (which) g_W2T[c * WS + k] = outv;
                        else       g_WcT[c * WS + k] = outv;
                    }
                }
            }
    } else if (w < NC) {
        const float4* fb = (const float4*)feat_b;
        const float4* cv = swv + w * 384;
        float s = 0.f;
        #pragma unroll 4
        for (int it = 0; it < 12; it++) {
            int col = it * 32 + lane;
            float4 a = fb[col], b = cv[col];
            s += a.x * b.x + a.y * b.y + a.z * b.z + a.w * b.w;
        }
        #pragma unroll
        for (int o = 16; o; o >>= 1) s += __shfl_down_sync(0xffffffffu, s, o);
        if (lane == 0) { if (which) g_fbW2[w] = s; else g_fbc[w] = s; }
    }
}

// ================= kA: pp0 (blocks 0..11) || dotW0 (blocks 12..61) =================
__global__ void __launch_bounds__(512) kA(const float* __restrict__ hidden,
                                          const float* __restrict__ cls_w,
                                          const float* __restrict__ cls_b,
                                          const float* __restrict__ am,
                                          const float* __restrict__ feat_w,
                                          const float* __restrict__ feat_b) {
    __shared__ float sbuf[9216];                     // 36 KB
    int tid = threadIdx.x;
    if (blockIdx.x >= 12) {
        dotW_body(sbuf, blockIdx.x - 12, feat_w, feat_b, cls_w, 0);
        return;
    }
    // ---- pp0: hop0 p0/q0 + masked max-pool, dot split over 2 half-threads ----
    int b = blockIdx.x / NC, c = blockIdx.x % NC;
    float* sw  = sbuf;          // 1536
    float* sp  = sbuf + 1536;
    float* sq  = sbuf + 1664;
    float* smm = sbuf + 1792;
    float* sm1 = sbuf + 1920;
    float* sm2 = sbuf + 2048;
    float* part = sbuf + 2176;  // 512
    for (int e = tid; e < 1536; e += 512) sw[e] = cls_w[e * NC + c];
    __syncthreads();
    int k = tid & 127, isq = (tid >> 7) & 1, hh = tid >> 8;
    {
        const float4* hr = (const float4*)(hidden + (size_t)(b * LL + k) * 768);
        const float4* w4 = (const float4*)(sw + isq * 768);
        float s = 0.f;
        #pragma unroll 8
        for (int it = 0; it < 96; it++) {
            int col = hh * 96 + it;
            float4 a = hr[col], x = w4[col];
            s += a.x * x.x + a.y * x.y + a.z * x.z + a.w * x.w;
        }
        part[tid] = s;
    }
    __syncthreads();
    if (tid < 256) {
        float s2 = part[tid] + part[tid + 256];
        if (isq) sq[k] = s2; else { sp[k] = s2; smm[k] = am[b * LL + k]; }
    }
    __syncthreads();
    float r = cls_b[c];
    if (tid < 256) {
        float mk = smm[k], pk = sp[k], qk = sq[k];
        float mx = -INFINITY;
        if (isq == 0) {                              // column k: over i <= k
            #pragma unroll 4
            for (int i = 0; i < LL; i++) {
                float mv = (i <= k) ? smm[i] * mk : 0.f;
                mx = fmaxf(mx, (sp[i] + qk + r) * mv);
            }
            sm1[k] = mx;
        } else {                                     // row k: over j >= k
            #pragma unroll 4
            for (int i = 0; i < LL; i++) {
                float mv = (i >= k) ? mk * smm[i] : 0.f;
                mx = fmaxf(mx, (pk + sq[i] + r) * mv);
            }
            sm2[k] = mx;
        }
    }
    __syncthreads();
    if (tid < 256 && isq == 0) {
        int rw = b * LL + k;
        g_pool0[rw * NC + c] = fmaxf(sm1[k], sm2[k]);
        g_pqr0[rw * NC + c] = sp[k];
        g_pqr0[(256 + rw) * NC + c] = sq[k];
        if (b == 0 && k == 0) g_pqr0[512 * NC + c] = r;
    }
}

// ================= kB: dotW1 (blocks 0..49) || probs1 (blocks 50..306, 2 rows each) ====
__global__ void __launch_bounds__(512) kB(const float* __restrict__ hidden,
                                          const float* __restrict__ cls_w,
                                          const float* __restrict__ cls_b,
                                          const float* __restrict__ feat_w,
                                          const float* __restrict__ feat_b) {
    __shared__ float sbuf[9216];
    if (blockIdx.x < 50) {
        dotW_body(sbuf, blockIdx.x, feat_w, feat_b, cls_w, 1);
        return;
    }
    int w = threadIdx.x >> 5, lane = threadIdx.x & 31;
    if (w >= 12) return;
    int row = (blockIdx.x - 50) * 2 + (w / 6);
    int c = w % 6;
    if (row >= 513) return;
    float s = 0.f;
    if (row < 512) {
        const float4* hr = (const float4*)(hidden + (size_t)(row < 256 ? row : row - 256) * 768);
        const float4* wr = (const float4*)(g_WcT + (size_t)c * WS + (row < 256 ? 0 : 768));
        #pragma unroll
        for (int it = 0; it < 6; it++) {
            int k4 = it * 32 + lane;
            float4 a = hr[k4], b = wr[k4];
            s += a.x * b.x + a.y * b.y + a.z * b.z + a.w * b.w;
        }
    }
    #pragma unroll
    for (int o = 16; o; o >>= 1) s += __shfl_down_sync(0xffffffffu, s, o);
    if (lane == 0) {
        const float* wt = g_WcT + (size_t)c * WS + 1536;
        if (row < 256) {
            #pragma unroll
            for (int t = 0; t < 6; t++) s += g_pool0[row * NC + t] * wt[t];
        } else if (row < 512) {
            #pragma unroll
            for (int t = 0; t < 6; t++) s += g_pool0[(row - 256) * NC + t] * wt[6 + t];
        }
        #pragma unroll
        for (int t = 0; t < 6; t++) s += g_pqr0[row * NC + t] * wt[12 + t];
        if (row == 512) s += g_fbc[c] + cls_b[c];
        g_pqr1[row * NC + c] = s;
    }
}

// ================= kC: probs2 with inline pool1 (513 blocks x 192) =================
__global__ void kC(const float* __restrict__ hidden, const float* __restrict__ cls_b,
                   const float* __restrict__ am) {
    __shared__ float spool[NC];
    int row = blockIdx.x;
    int c = threadIdx.x >> 5, lane = threadIdx.x & 31;
    float s = 0.f;
    if (row < 512) {
        const float4* hr = (const float4*)(hidden + (size_t)(row < 256 ? row : row - 256) * 768);
        const float4* wr = (const float4*)(g_W2T + (size_t)c * WS + (row < 256 ? 0 : 768));
        #pragma unroll
        for (int it = 0; it < 6; it++) {
            int k4 = it * 32 + lane;
            float4 a = hr[k4], b = wr[k4];
            s += a.x * b.x + a.y * b.y + a.z * b.z + a.w * b.w;
        }
    }
    #pragma unroll
    for (int o = 16; o; o >>= 1) s += __shfl_down_sync(0xffffffffu, s, o);
    // warp c computes pooled1[rw][c] from pqr1 (exact same mask/max as reference)
    if (row < 512) {
        int rw = (row < 256) ? row : row - 256;
        int b = rw >> 7, k = rw & 127;
        float mk  = am[b * LL + k];
        float pk1 = g_pqr1[(b * LL + k) * NC + c];
        float qk1 = g_pqr1[(256 + b * LL + k) * NC + c];
        float r1  = g_pqr1[512 * NC + c];
        float mx = -INFINITY;
        #pragma unroll
        for (int u = 0; u < 4; u++) {
            int i = lane + u * 32;
            float mi = am[b * LL + i];
            float mv1 = (i <= k) ? mi * mk : 0.f;    // column k over i
            mx = fmaxf(mx, (g_pqr1[(b * LL + i) * NC + c] + qk1 + r1) * mv1);
            float mv2 = (i >= k) ? mk * mi : 0.f;    // row k over j
            mx = fmaxf(mx, (pk1 + g_pqr1[(256 + b * LL + i) * NC + c] + r1) * mv2);
        }
        #pragma unroll
        for (int o = 16; o; o >>= 1) mx = fmaxf(mx, __shfl_down_sync(0xffffffffu, mx, o));
        if (lane == 0) spool[c] = mx;
    }
    __syncthreads();
    if (lane == 0) {
        const float* w2t = g_W2T + (size_t)c * WS + 1536;
        const float* wct = g_WcT + (size_t)c * WS + 1536;
        if (row < 256) {
            #pragma unroll
            for (int t = 0; t < 6; t++)
                s += g_pool0[row * NC + t] * w2t[t] + spool[t] * wct[t];
        } else if (row < 512) {
            #pragma unroll
            for (int t = 0; t < 6; t++)
                s += g_pool0[(row - 256) * NC + t] * w2t[6 + t] + spool[t] * wct[6 + t];
        }
        #pragma unroll
        for (int t = 0; t < 6; t++)
            s += g_pqr0[row * NC + t] * w2t[12 + t] + g_pqr1[row * NC + t] * wct[12 + t];
        if (row == 512) s += g_fbW2[c] + g_fbc[c] + cls_b[c];
        g_pqr2f[row * NC + c] = s;
    }
}

// ================= kD: logits — one block per (b,i), fully coalesced =================
// out[((b*128+i)*128+j)*6+c] = p[b,i,c] + q[b,j,c] + r[c]
__global__ void __launch_bounds__(192) k_out(float* __restrict__ out) {
    __shared__ float qr[768];                        // q[b,j,c] + r[c] for this b
    __shared__ float ps[NC];
    int blk = blockIdx.x;                            // 0..255 = b*128 + i
    int b = blk >> 7, i = blk & 127;
    int t = threadIdx.x;                             // 0..191
    // stage qr: q-rows for this b are 768 contiguous floats at (256 + b*128)*6
    {
        const float4* qv = (const float4*)(g_pqr2f + (size_t)(256 + b * LL) * NC);
        float4 v = qv[t];
        int e = t * 4;
        v.x += g_pqr2f[512 * NC + (e    ) % NC];
        v.y += g_pqr2f[512 * NC + (e + 1) % NC];
        v.z += g_pqr2f[512 * NC + (e + 2) % NC];
        v.w += g_pqr2f[512 * NC + (e + 3) % NC];
        *(float4*)(qr + e) = v;
    }
    if (t < NC) ps[t] = g_pqr2f[(size_t)(b * LL + i) * NC + t];
    __syncthreads();
    int e = t * 4;
    float4 o;
    o.x = qr[e]     + ps[(e    ) % NC];
    o.y = qr[e + 1] + ps[(e + 1) % NC];
    o.z = qr[e + 2] + ps[(e + 2) % NC];
    o.w = qr[e + 3] + ps[(e + 3) % NC];
    *(float4*)(out + (size_t)blk * 768 + e) = o;
}

extern "C" void kernel_launch(void* const* d_in, const int* in_sizes, int n_in,
                              void* d_out, int out_size) {
    const float* hidden = (const float*)d_in[0];
    const float* am     = (const float*)d_in[1];
    const float* cls_w  = (const float*)d_in[2];
    const float* cls_b  = (const float*)d_in[3];
    const float* feat_w = (const float*)d_in[4];
    const float* feat_b = (const float*)d_in[5];

    kA<<<62, 512>>>(hidden, cls_w, cls_b, am, feat_w, feat_b);   // pp0 || Wc
    kB<<<307, 512>>>(hidden, cls_w, cls_b, feat_w, feat_b);      // W2 || probs1
    kC<<<513, 192>>>(hidden, cls_b, am);                         // probs2 + inline pool1
    k_out<<<256, 192>>>((float*)d_out);                          // logits (coalesced)
}